// round 1
// baseline (speedup 1.0000x reference)
#include <cuda_runtime.h>
#include <cstdint>
#include <cstddef>

#define N_NODES 100000
#define N_EDGES 20000
#define F 128

// ---------------- scratch (static device globals; no allocation) -------------
__device__ float g_node_msg[(size_t)N_NODES * F];   // sigmoid(x0 @ Wnh^T + b)
__device__ float g_edge_agg[(size_t)N_EDGES * F];   // segment-sum onto edges
__device__ float g_he_msg[(size_t)N_EDGES * F];     // sigmoid(cat(x1,agg) @ Wen^T + b)
__device__ float g_node_agg[(size_t)N_NODES * F];   // segment-sum onto nodes

__device__ __forceinline__ float sigmoidf(float x) {
    return 1.0f / (1.0f + __expf(-x));
}

// ---------------- zero fill --------------------------------------------------
__global__ void zero_kernel(float4* __restrict__ p, int n4) {
    int i = blockIdx.x * blockDim.x + threadIdx.x;
    if (i < n4) p[i] = make_float4(0.f, 0.f, 0.f, 0.f);
}

// ---------------- fused GEMM + bias + sigmoid --------------------------------
// out[m][n] = sigmoid( sum_k XA[m][k]*W[n][k]  (k in 0..127)
//                    + sum_k XB[m][k]*W[n][128+k]  (if TWO)
//                    + bias[n] )
// W is row-major [128][ldw]. BM=128 rows, BN=128 cols (all), BK=16.
// 256 threads, each computes an 8x8 register tile.
template <bool TWO>
__global__ void __launch_bounds__(256) gemm_sig_kernel(
    const float* __restrict__ XA, const float* __restrict__ XB,
    const float* __restrict__ W, int ldw,
    const float* __restrict__ bias,
    float* __restrict__ out, int M)
{
    __shared__ float Xs[16][128];   // Xs[k][m]
    __shared__ float Ws[16][128];   // Ws[k][n]

    const int t  = threadIdx.x;
    const int tx = t & 15;          // col group
    const int ty = t >> 4;          // row group
    const int m0 = blockIdx.x * 128;

    float acc[8][8];
#pragma unroll
    for (int r = 0; r < 8; r++)
#pragma unroll
        for (int c = 0; c < 8; c++) acc[r][c] = 0.f;

    const int KTOT = TWO ? 256 : 128;
    for (int kc = 0; kc < KTOT; kc += 16) {
        const float* Xsrc;
        int koff;
        if (TWO && kc >= 128) { Xsrc = XB; koff = kc - 128; }
        else                  { Xsrc = XA; koff = kc; }

        // load X tile (transposed into smem): 2048 floats = 512 float4
#pragma unroll
        for (int it = 0; it < 2; it++) {
            int li = t + it * 256;        // 0..511
            int m  = li >> 2;             // 0..127
            int kq = li & 3;              // which float4 along k
            float4 v = make_float4(0.f, 0.f, 0.f, 0.f);
            if (m0 + m < M)
                v = *(const float4*)(Xsrc + (size_t)(m0 + m) * F + koff + kq * 4);
            Xs[kq * 4 + 0][m] = v.x;
            Xs[kq * 4 + 1][m] = v.y;
            Xs[kq * 4 + 2][m] = v.z;
            Xs[kq * 4 + 3][m] = v.w;
        }
        // load W tile (transposed)
#pragma unroll
        for (int it = 0; it < 2; it++) {
            int li = t + it * 256;
            int n  = li >> 2;
            int kq = li & 3;
            float4 v = *(const float4*)(W + (size_t)n * ldw + kc + kq * 4);
            Ws[kq * 4 + 0][n] = v.x;
            Ws[kq * 4 + 1][n] = v.y;
            Ws[kq * 4 + 2][n] = v.z;
            Ws[kq * 4 + 3][n] = v.w;
        }
        __syncthreads();

#pragma unroll
        for (int kk = 0; kk < 16; kk++) {
            float a[8], b[8];
            *(float4*)&a[0] = *(const float4*)&Xs[kk][ty * 8];
            *(float4*)&a[4] = *(const float4*)&Xs[kk][ty * 8 + 4];
            *(float4*)&b[0] = *(const float4*)&Ws[kk][tx * 8];
            *(float4*)&b[4] = *(const float4*)&Ws[kk][tx * 8 + 4];
#pragma unroll
            for (int r = 0; r < 8; r++)
#pragma unroll
                for (int c = 0; c < 8; c++)
                    acc[r][c] += a[r] * b[c];
        }
        __syncthreads();
    }

    // epilogue: + bias, sigmoid, store
    float bb[8];
    *(float4*)&bb[0] = *(const float4*)(bias + tx * 8);
    *(float4*)&bb[4] = *(const float4*)(bias + tx * 8 + 4);

#pragma unroll
    for (int r = 0; r < 8; r++) {
        int m = m0 + ty * 8 + r;
        if (m < M) {
            float4 o0, o1;
            o0.x = sigmoidf(acc[r][0] + bb[0]);
            o0.y = sigmoidf(acc[r][1] + bb[1]);
            o0.z = sigmoidf(acc[r][2] + bb[2]);
            o0.w = sigmoidf(acc[r][3] + bb[3]);
            o1.x = sigmoidf(acc[r][4] + bb[4]);
            o1.y = sigmoidf(acc[r][5] + bb[5]);
            o1.z = sigmoidf(acc[r][6] + bb[6]);
            o1.w = sigmoidf(acc[r][7] + bb[7]);
            *(float4*)(out + (size_t)m * F + tx * 8)     = o0;
            *(float4*)(out + (size_t)m * F + tx * 8 + 4) = o1;
        }
    }
}

// ---------------- scatter-add over incidence pairs ---------------------------
// one warp per pair: gather src[sidx[p]][:] (32 x float4), red.add into
// dst[didx[p]][:]. Vectorized reduction (red.global.add.v4.f32, sm_90+).
__global__ void __launch_bounds__(256) scatter_kernel(
    const float* __restrict__ src,
    const int* __restrict__ sidx,
    const int* __restrict__ didx,
    float* __restrict__ dst, int nnz)
{
    int w = (int)((blockIdx.x * (size_t)blockDim.x + threadIdx.x) >> 5);
    if (w >= nnz) return;
    int lane = threadIdx.x & 31;
    int s = __ldg(sidx + w);   // same address within warp -> broadcast
    int d = __ldg(didx + w);
    const float4 v = __ldg((const float4*)src + (size_t)s * 32 + lane);
    float4* p = (float4*)dst + (size_t)d * 32 + lane;
    asm volatile("red.global.add.v4.f32 [%0], {%1, %2, %3, %4};"
                 :: "l"(p), "f"(v.x), "f"(v.y), "f"(v.z), "f"(v.w)
                 : "memory");
}

// ---------------- finalize: sigmoid(bn(x) + agg) -----------------------------
__global__ void __launch_bounds__(256) finalize_kernel(
    const float4* __restrict__ x, const float4* __restrict__ agg,
    const float* __restrict__ gamma, const float* __restrict__ beta,
    const float* __restrict__ mean, const float* __restrict__ var,
    float4* __restrict__ out, int n4)
{
    int i = blockIdx.x * blockDim.x + threadIdx.x;
    if (i >= n4) return;
    int fb = (i & 31) * 4;   // feature base (row stride = 128 floats = 32 f4)
    float4 xv = x[i];
    float4 av = agg[i];
    float4 o;
    {
        float s = gamma[fb + 0] * rsqrtf(var[fb + 0] + 1e-5f);
        o.x = sigmoidf((xv.x - mean[fb + 0]) * s + beta[fb + 0] + av.x);
    }
    {
        float s = gamma[fb + 1] * rsqrtf(var[fb + 1] + 1e-5f);
        o.y = sigmoidf((xv.y - mean[fb + 1]) * s + beta[fb + 1] + av.y);
    }
    {
        float s = gamma[fb + 2] * rsqrtf(var[fb + 2] + 1e-5f);
        o.z = sigmoidf((xv.z - mean[fb + 2]) * s + beta[fb + 2] + av.z);
    }
    {
        float s = gamma[fb + 3] * rsqrtf(var[fb + 3] + 1e-5f);
        o.w = sigmoidf((xv.w - mean[fb + 3]) * s + beta[fb + 3] + av.w);
    }
    out[i] = o;
}

// ---------------- launch -----------------------------------------------------
extern "C" void kernel_launch(void* const* d_in, const int* in_sizes, int n_in,
                              void* d_out, int out_size)
{
    const float* x0        = (const float*)d_in[0];
    const float* x1        = (const float*)d_in[1];
    const int*   node_idx  = (const int*)d_in[2];
    const int*   edge_idx  = (const int*)d_in[3];
    const float* W_nh      = (const float*)d_in[4];
    const float* b_nh      = (const float*)d_in[5];
    const float* W_en      = (const float*)d_in[6];
    const float* b_en      = (const float*)d_in[7];
    const float* bn0_gamma = (const float*)d_in[8];
    const float* bn0_beta  = (const float*)d_in[9];
    const float* bn0_mean  = (const float*)d_in[10];
    const float* bn0_var   = (const float*)d_in[11];
    const float* bn1_gamma = (const float*)d_in[12];
    const float* bn1_beta  = (const float*)d_in[13];
    const float* bn1_mean  = (const float*)d_in[14];
    const float* bn1_var   = (const float*)d_in[15];

    float* out = (float*)d_out;
    const int nnz = in_sizes[2];

    float *node_msg, *edge_agg, *he_msg, *node_agg;
    cudaGetSymbolAddress((void**)&node_msg, g_node_msg);
    cudaGetSymbolAddress((void**)&edge_agg, g_edge_agg);
    cudaGetSymbolAddress((void**)&he_msg,  g_he_msg);
    cudaGetSymbolAddress((void**)&node_agg, g_node_agg);

    // zero the two accumulation buffers
    {
        int n4 = N_EDGES * F / 4;
        zero_kernel<<<(n4 + 255) / 256, 256>>>((float4*)edge_agg, n4);
    }
    {
        int n4 = N_NODES * F / 4;
        zero_kernel<<<(n4 + 255) / 256, 256>>>((float4*)node_agg, n4);
    }

    // 1) node messages: sigmoid(x0 @ Wnh^T + b)
    gemm_sig_kernel<false><<<(N_NODES + 127) / 128, 256>>>(
        x0, nullptr, W_nh, 128, b_nh, node_msg, N_NODES);

    // 2) scatter node messages onto edges
    {
        long long threads = (long long)nnz * 32;
        int blocks = (int)((threads + 255) / 256);
        scatter_kernel<<<blocks, 256>>>(node_msg, node_idx, edge_idx, edge_agg, nnz);
    }

    // 3) hyperedge messages: sigmoid(cat(x1, edge_agg) @ Wen^T + b)
    gemm_sig_kernel<true><<<(N_EDGES + 127) / 128, 256>>>(
        x1, edge_agg, W_en, 256, b_en, he_msg, N_EDGES);

    // 4) scatter hyperedge messages onto nodes
    {
        long long threads = (long long)nnz * 32;
        int blocks = (int)((threads + 255) / 256);
        scatter_kernel<<<blocks, 256>>>(he_msg, edge_idx, node_idx, node_agg, nnz);
    }

    // 5) finalize outputs
    {
        int n4 = N_NODES * F / 4;
        finalize_kernel<<<(n4 + 255) / 256, 256>>>(
            (const float4*)x0, (const float4*)node_agg,
            bn0_gamma, bn0_beta, bn0_mean, bn0_var,
            (float4*)out, n4);
    }
    {
        int n4 = N_EDGES * F / 4;
        finalize_kernel<<<(n4 + 255) / 256, 256>>>(
            (const float4*)x1, (const float4*)edge_agg,
            bn1_gamma, bn1_beta, bn1_mean, bn1_var,
            (float4*)(out + (size_t)N_NODES * F), n4);
    }
}

// round 2
// speedup vs baseline: 1.5335x; 1.5335x over previous
#include <cuda_runtime.h>
#include <cstdint>
#include <cstddef>

#define N_NODES 100000
#define N_EDGES 20000
#define F 128
#define NNZ_MAX 2000000
#define NSEG (N_EDGES + N_NODES)          // 120000 segments (edges first)
#define SCAN_BLK 1024
#define NBLK ((NSEG + SCAN_BLK - 1) / SCAN_BLK)   // 118

// ---------------- scratch (static device globals; no allocation) -------------
__device__ float g_node_msg[(size_t)N_NODES * F];
__device__ float g_edge_agg[(size_t)N_EDGES * F];
__device__ float g_he_msg[(size_t)N_EDGES * F];
__device__ float g_node_agg[(size_t)N_NODES * F];
__device__ int   g_cnt[NSEG];
__device__ int   g_excl[NSEG];
__device__ int   g_blksum[NBLK];
__device__ int   g_blkoff[NBLK];
__device__ int   g_offsets[NSEG + 1];
__device__ int   g_cursors[NSEG];
__device__ int   g_entries[2 * NNZ_MAX];   // [0,nnz): per-edge lists; [nnz,2nnz): per-node

__device__ __forceinline__ float sigmoidf(float x) {
    return 1.0f / (1.0f + __expf(-x));
}

// ---------------- CSR build --------------------------------------------------
__global__ void zero_int_kernel(int* __restrict__ p, int n) {
    int i = blockIdx.x * blockDim.x + threadIdx.x;
    if (i < n) p[i] = 0;
}

__global__ void hist_kernel(const int* __restrict__ node_idx,
                            const int* __restrict__ edge_idx,
                            int* __restrict__ cnt, int nnz) {
    int p = blockIdx.x * blockDim.x + threadIdx.x;
    if (p >= nnz) return;
    atomicAdd(&cnt[edge_idx[p]], 1);               // edge segment
    atomicAdd(&cnt[N_EDGES + node_idx[p]], 1);     // node segment
}

// per-block exclusive scan (Hillis-Steele in smem) + block sums
__global__ void scan1_kernel(const int* __restrict__ cnt, int* __restrict__ excl,
                             int* __restrict__ blksum, int n) {
    __shared__ int sh[SCAN_BLK];
    int tid = threadIdx.x;
    int i = blockIdx.x * SCAN_BLK + tid;
    int v = (i < n) ? cnt[i] : 0;
    sh[tid] = v;
    __syncthreads();
#pragma unroll
    for (int ofs = 1; ofs < SCAN_BLK; ofs <<= 1) {
        int add = (tid >= ofs) ? sh[tid - ofs] : 0;
        __syncthreads();
        sh[tid] += add;
        __syncthreads();
    }
    if (i < n) excl[i] = sh[tid] - v;
    if (tid == SCAN_BLK - 1) blksum[blockIdx.x] = sh[tid];
}

// single-block exclusive scan of the (<=128) block sums
__global__ void scan2_kernel(const int* __restrict__ blksum,
                             int* __restrict__ blkoff, int nblk) {
    __shared__ int sh[128];
    int tid = threadIdx.x;
    int v = (tid < nblk) ? blksum[tid] : 0;
    sh[tid] = v;
    __syncthreads();
#pragma unroll
    for (int ofs = 1; ofs < 128; ofs <<= 1) {
        int add = (tid >= ofs) ? sh[tid - ofs] : 0;
        __syncthreads();
        sh[tid] += add;
        __syncthreads();
    }
    if (tid < nblk) blkoff[tid] = sh[tid] - v;
}

// offsets = excl + blkoff, cursors = offsets, offsets[NSEG] = 2*nnz
__global__ void scan3_kernel(const int* __restrict__ excl,
                             const int* __restrict__ blkoff,
                             int* __restrict__ offsets,
                             int* __restrict__ cursors, int n, int total) {
    int i = blockIdx.x * blockDim.x + threadIdx.x;
    if (i < n) {
        int o = excl[i] + blkoff[i / SCAN_BLK];
        offsets[i] = o;
        cursors[i] = o;
    }
    if (i == 0) offsets[n] = total;
}

__global__ void fill_kernel(const int* __restrict__ node_idx,
                            const int* __restrict__ edge_idx,
                            int* __restrict__ cursors,
                            int* __restrict__ entries, int nnz) {
    int p = blockIdx.x * blockDim.x + threadIdx.x;
    if (p >= nnz) return;
    int n = node_idx[p];
    int e = edge_idx[p];
    int s1 = atomicAdd(&cursors[e], 1);
    entries[s1] = n;                        // edge segment -> list of nodes
    int s2 = atomicAdd(&cursors[N_EDGES + n], 1);
    entries[s2] = e;                        // node segment -> list of edges
}

// ---------------- atomic-free segment sum ------------------------------------
// one warp per segment, lane = float4 column of the 128-float row.
__global__ void __launch_bounds__(256) segsum_kernel(
    const float4* __restrict__ src,
    const int* __restrict__ entries,
    const int* __restrict__ offsets, int segbase,
    float4* __restrict__ dst, int nseg)
{
    int w = (int)((blockIdx.x * (size_t)blockDim.x + threadIdx.x) >> 5);
    if (w >= nseg) return;
    int lane = threadIdx.x & 31;
    int beg = __ldg(offsets + segbase + w);
    int end = __ldg(offsets + segbase + w + 1);

    float4 a0 = make_float4(0.f, 0.f, 0.f, 0.f);
    float4 a1 = a0, a2 = a0, a3 = a0;

    int j = beg;
    for (; j + 4 <= end; j += 4) {
        int e0 = __ldg(entries + j);
        int e1 = __ldg(entries + j + 1);
        int e2 = __ldg(entries + j + 2);
        int e3 = __ldg(entries + j + 3);
        float4 v0 = __ldg(src + (size_t)e0 * 32 + lane);
        float4 v1 = __ldg(src + (size_t)e1 * 32 + lane);
        float4 v2 = __ldg(src + (size_t)e2 * 32 + lane);
        float4 v3 = __ldg(src + (size_t)e3 * 32 + lane);
        a0.x += v0.x; a0.y += v0.y; a0.z += v0.z; a0.w += v0.w;
        a1.x += v1.x; a1.y += v1.y; a1.z += v1.z; a1.w += v1.w;
        a2.x += v2.x; a2.y += v2.y; a2.z += v2.z; a2.w += v2.w;
        a3.x += v3.x; a3.y += v3.y; a3.z += v3.z; a3.w += v3.w;
    }
    for (; j < end; j++) {
        int e = __ldg(entries + j);
        float4 v = __ldg(src + (size_t)e * 32 + lane);
        a0.x += v.x; a0.y += v.y; a0.z += v.z; a0.w += v.w;
    }
    float4 r;
    r.x = (a0.x + a1.x) + (a2.x + a3.x);
    r.y = (a0.y + a1.y) + (a2.y + a3.y);
    r.z = (a0.z + a1.z) + (a2.z + a3.z);
    r.w = (a0.w + a1.w) + (a2.w + a3.w);
    dst[(size_t)w * 32 + lane] = r;
}

// ---------------- fused GEMM + bias + sigmoid --------------------------------
template <bool TWO>
__global__ void __launch_bounds__(256) gemm_sig_kernel(
    const float* __restrict__ XA, const float* __restrict__ XB,
    const float* __restrict__ W, int ldw,
    const float* __restrict__ bias,
    float* __restrict__ out, int M)
{
    __shared__ float Xs[16][128];   // Xs[k][m]
    __shared__ float Ws[16][128];   // Ws[k][n]

    const int t  = threadIdx.x;
    const int tx = t & 15;
    const int ty = t >> 4;
    const int m0 = blockIdx.x * 128;

    float acc[8][8];
#pragma unroll
    for (int r = 0; r < 8; r++)
#pragma unroll
        for (int c = 0; c < 8; c++) acc[r][c] = 0.f;

    const int KTOT = TWO ? 256 : 128;
    for (int kc = 0; kc < KTOT; kc += 16) {
        const float* Xsrc;
        int koff;
        if (TWO && kc >= 128) { Xsrc = XB; koff = kc - 128; }
        else                  { Xsrc = XA; koff = kc; }

#pragma unroll
        for (int it = 0; it < 2; it++) {
            int li = t + it * 256;
            int m  = li >> 2;
            int kq = li & 3;
            float4 v = make_float4(0.f, 0.f, 0.f, 0.f);
            if (m0 + m < M)
                v = *(const float4*)(Xsrc + (size_t)(m0 + m) * F + koff + kq * 4);
            Xs[kq * 4 + 0][m] = v.x;
            Xs[kq * 4 + 1][m] = v.y;
            Xs[kq * 4 + 2][m] = v.z;
            Xs[kq * 4 + 3][m] = v.w;
        }
#pragma unroll
        for (int it = 0; it < 2; it++) {
            int li = t + it * 256;
            int n  = li >> 2;
            int kq = li & 3;
            float4 v = *(const float4*)(W + (size_t)n * ldw + kc + kq * 4);
            Ws[kq * 4 + 0][n] = v.x;
            Ws[kq * 4 + 1][n] = v.y;
            Ws[kq * 4 + 2][n] = v.z;
            Ws[kq * 4 + 3][n] = v.w;
        }
        __syncthreads();

#pragma unroll
        for (int kk = 0; kk < 16; kk++) {
            float a[8], b[8];
            *(float4*)&a[0] = *(const float4*)&Xs[kk][ty * 8];
            *(float4*)&a[4] = *(const float4*)&Xs[kk][ty * 8 + 4];
            *(float4*)&b[0] = *(const float4*)&Ws[kk][tx * 8];
            *(float4*)&b[4] = *(const float4*)&Ws[kk][tx * 8 + 4];
#pragma unroll
            for (int r = 0; r < 8; r++)
#pragma unroll
                for (int c = 0; c < 8; c++)
                    acc[r][c] += a[r] * b[c];
        }
        __syncthreads();
    }

    float bb[8];
    *(float4*)&bb[0] = *(const float4*)(bias + tx * 8);
    *(float4*)&bb[4] = *(const float4*)(bias + tx * 8 + 4);

#pragma unroll
    for (int r = 0; r < 8; r++) {
        int m = m0 + ty * 8 + r;
        if (m < M) {
            float4 o0, o1;
            o0.x = sigmoidf(acc[r][0] + bb[0]);
            o0.y = sigmoidf(acc[r][1] + bb[1]);
            o0.z = sigmoidf(acc[r][2] + bb[2]);
            o0.w = sigmoidf(acc[r][3] + bb[3]);
            o1.x = sigmoidf(acc[r][4] + bb[4]);
            o1.y = sigmoidf(acc[r][5] + bb[5]);
            o1.z = sigmoidf(acc[r][6] + bb[6]);
            o1.w = sigmoidf(acc[r][7] + bb[7]);
            *(float4*)(out + (size_t)m * F + tx * 8)     = o0;
            *(float4*)(out + (size_t)m * F + tx * 8 + 4) = o1;
        }
    }
}

// ---------------- finalize: sigmoid(bn(x) + agg) -----------------------------
__global__ void __launch_bounds__(256) finalize_kernel(
    const float4* __restrict__ x, const float4* __restrict__ agg,
    const float* __restrict__ gamma, const float* __restrict__ beta,
    const float* __restrict__ mean, const float* __restrict__ var,
    float4* __restrict__ out, int n4)
{
    int i = blockIdx.x * blockDim.x + threadIdx.x;
    if (i >= n4) return;
    int fb = (i & 31) * 4;
    float4 xv = x[i];
    float4 av = agg[i];
    float4 o;
    {
        float s = gamma[fb + 0] * rsqrtf(var[fb + 0] + 1e-5f);
        o.x = sigmoidf((xv.x - mean[fb + 0]) * s + beta[fb + 0] + av.x);
    }
    {
        float s = gamma[fb + 1] * rsqrtf(var[fb + 1] + 1e-5f);
        o.y = sigmoidf((xv.y - mean[fb + 1]) * s + beta[fb + 1] + av.y);
    }
    {
        float s = gamma[fb + 2] * rsqrtf(var[fb + 2] + 1e-5f);
        o.z = sigmoidf((xv.z - mean[fb + 2]) * s + beta[fb + 2] + av.z);
    }
    {
        float s = gamma[fb + 3] * rsqrtf(var[fb + 3] + 1e-5f);
        o.w = sigmoidf((xv.w - mean[fb + 3]) * s + beta[fb + 3] + av.w);
    }
    out[i] = o;
}

// ---------------- launch -----------------------------------------------------
extern "C" void kernel_launch(void* const* d_in, const int* in_sizes, int n_in,
                              void* d_out, int out_size)
{
    const float* x0        = (const float*)d_in[0];
    const float* x1        = (const float*)d_in[1];
    const int*   node_idx  = (const int*)d_in[2];
    const int*   edge_idx  = (const int*)d_in[3];
    const float* W_nh      = (const float*)d_in[4];
    const float* b_nh      = (const float*)d_in[5];
    const float* W_en      = (const float*)d_in[6];
    const float* b_en      = (const float*)d_in[7];
    const float* bn0_gamma = (const float*)d_in[8];
    const float* bn0_beta  = (const float*)d_in[9];
    const float* bn0_mean  = (const float*)d_in[10];
    const float* bn0_var   = (const float*)d_in[11];
    const float* bn1_gamma = (const float*)d_in[12];
    const float* bn1_beta  = (const float*)d_in[13];
    const float* bn1_mean  = (const float*)d_in[14];
    const float* bn1_var   = (const float*)d_in[15];

    float* out = (float*)d_out;
    const int nnz = in_sizes[2];

    float *node_msg, *edge_agg, *he_msg, *node_agg;
    int *cnt, *excl, *blksum, *blkoff, *offsets, *cursors, *entries;
    cudaGetSymbolAddress((void**)&node_msg, g_node_msg);
    cudaGetSymbolAddress((void**)&edge_agg, g_edge_agg);
    cudaGetSymbolAddress((void**)&he_msg,  g_he_msg);
    cudaGetSymbolAddress((void**)&node_agg, g_node_agg);
    cudaGetSymbolAddress((void**)&cnt,     g_cnt);
    cudaGetSymbolAddress((void**)&excl,    g_excl);
    cudaGetSymbolAddress((void**)&blksum,  g_blksum);
    cudaGetSymbolAddress((void**)&blkoff,  g_blkoff);
    cudaGetSymbolAddress((void**)&offsets, g_offsets);
    cudaGetSymbolAddress((void**)&cursors, g_cursors);
    cudaGetSymbolAddress((void**)&entries, g_entries);

    // --- CSR build ---
    zero_int_kernel<<<(NSEG + 255) / 256, 256>>>(cnt, NSEG);
    hist_kernel<<<(nnz + 255) / 256, 256>>>(node_idx, edge_idx, cnt, nnz);
    scan1_kernel<<<NBLK, SCAN_BLK>>>(cnt, excl, blksum, NSEG);
    scan2_kernel<<<1, 128>>>(blksum, blkoff, NBLK);
    scan3_kernel<<<(NSEG + 255) / 256, 256>>>(excl, blkoff, offsets, cursors,
                                              NSEG, 2 * nnz);
    fill_kernel<<<(nnz + 255) / 256, 256>>>(node_idx, edge_idx, cursors,
                                            entries, nnz);

    // 1) node messages: sigmoid(x0 @ Wnh^T + b)
    gemm_sig_kernel<false><<<(N_NODES + 127) / 128, 256>>>(
        x0, nullptr, W_nh, 128, b_nh, node_msg, N_NODES);

    // 2) per-edge segment sum of node messages (atomic-free)
    segsum_kernel<<<(N_EDGES * 32 + 255) / 256, 256>>>(
        (const float4*)node_msg, entries, offsets, 0,
        (float4*)edge_agg, N_EDGES);

    // 3) hyperedge messages: sigmoid(cat(x1, edge_agg) @ Wen^T + b)
    gemm_sig_kernel<true><<<(N_EDGES + 127) / 128, 256>>>(
        x1, edge_agg, W_en, 256, b_en, he_msg, N_EDGES);

    // 4) per-node segment sum of hyperedge messages (atomic-free)
    segsum_kernel<<<(N_NODES * 32 + 255) / 256, 256>>>(
        (const float4*)he_msg, entries, offsets, N_EDGES,
        (float4*)node_agg, N_NODES);

    // 5) finalize outputs
    {
        int n4 = N_NODES * F / 4;
        finalize_kernel<<<(n4 + 255) / 256, 256>>>(
            (const float4*)x0, (const float4*)node_agg,
            bn0_gamma, bn0_beta, bn0_mean, bn0_var,
            (float4*)out, n4);
    }
    {
        int n4 = N_EDGES * F / 4;
        finalize_kernel<<<(n4 + 255) / 256, 256>>>(
            (const float4*)x1, (const float4*)edge_agg,
            bn1_gamma, bn1_beta, bn1_mean, bn1_var,
            (float4*)(out + (size_t)N_NODES * F), n4);
    }
}

// round 3
// speedup vs baseline: 2.0789x; 1.3557x over previous
#include <cuda_runtime.h>
#include <cuda_fp16.h>
#include <cstdint>
#include <cstddef>

#define N_NODES 100000
#define N_EDGES 20000
#define F 128
#define NNZ_MAX 2000000
#define NSEG (N_EDGES + N_NODES)
#define SCAN_BLK 1024
#define NBLK ((NSEG + SCAN_BLK - 1) / SCAN_BLK)

// ---------------- scratch ----------------------------------------------------
__device__ __half g_node_msg[(size_t)N_NODES * F];
__device__ float  g_edge_agg[(size_t)N_EDGES * F];
__device__ __half g_he_msg[(size_t)N_EDGES * F];
__device__ int    g_cnt[NSEG];
__device__ int    g_excl[NSEG];
__device__ int    g_blksum[NBLK];
__device__ int    g_blkoff[NBLK];
__device__ int    g_offsets[NSEG + 1];
__device__ int    g_cursors[NSEG];
__device__ int    g_entries[2 * NNZ_MAX];

__device__ __forceinline__ float sigmoidf(float x) {
    return 1.0f / (1.0f + __expf(-x));
}
__device__ __forceinline__ uint32_t f2tf32(float f) {
    uint32_t r;
    asm("cvt.rna.tf32.f32 %0, %1;" : "=r"(r) : "f"(f));
    return r;
}
__device__ __forceinline__ void mma_tf32(float c[4],
    uint32_t a0, uint32_t a1, uint32_t a2, uint32_t a3,
    uint32_t b0, uint32_t b1)
{
    asm volatile(
        "mma.sync.aligned.m16n8k8.row.col.f32.tf32.tf32.f32 "
        "{%0,%1,%2,%3}, {%4,%5,%6,%7}, {%8,%9}, {%0,%1,%2,%3};"
        : "+f"(c[0]), "+f"(c[1]), "+f"(c[2]), "+f"(c[3])
        : "r"(a0), "r"(a1), "r"(a2), "r"(a3), "r"(b0), "r"(b1));
}

// ---------------- CSR build --------------------------------------------------
__global__ void zero_int_kernel(int* __restrict__ p, int n) {
    int i = blockIdx.x * blockDim.x + threadIdx.x;
    if (i < n) p[i] = 0;
}

__global__ void hist_kernel(const int* __restrict__ node_idx,
                            const int* __restrict__ edge_idx,
                            int* __restrict__ cnt, int nnz) {
    int p = blockIdx.x * blockDim.x + threadIdx.x;
    if (p >= nnz) return;
    atomicAdd(&cnt[edge_idx[p]], 1);
    atomicAdd(&cnt[N_EDGES + node_idx[p]], 1);
}

__global__ void scan1_kernel(const int* __restrict__ cnt, int* __restrict__ excl,
                             int* __restrict__ blksum, int n) {
    __shared__ int sh[SCAN_BLK];
    int tid = threadIdx.x;
    int i = blockIdx.x * SCAN_BLK + tid;
    int v = (i < n) ? cnt[i] : 0;
    sh[tid] = v;
    __syncthreads();
#pragma unroll
    for (int ofs = 1; ofs < SCAN_BLK; ofs <<= 1) {
        int add = (tid >= ofs) ? sh[tid - ofs] : 0;
        __syncthreads();
        sh[tid] += add;
        __syncthreads();
    }
    if (i < n) excl[i] = sh[tid] - v;
    if (tid == SCAN_BLK - 1) blksum[blockIdx.x] = sh[tid];
}

__global__ void scan2_kernel(const int* __restrict__ blksum,
                             int* __restrict__ blkoff, int nblk) {
    __shared__ int sh[128];
    int tid = threadIdx.x;
    int v = (tid < nblk) ? blksum[tid] : 0;
    sh[tid] = v;
    __syncthreads();
#pragma unroll
    for (int ofs = 1; ofs < 128; ofs <<= 1) {
        int add = (tid >= ofs) ? sh[tid - ofs] : 0;
        __syncthreads();
        sh[tid] += add;
        __syncthreads();
    }
    if (tid < nblk) blkoff[tid] = sh[tid] - v;
}

__global__ void scan3_kernel(const int* __restrict__ excl,
                             const int* __restrict__ blkoff,
                             int* __restrict__ offsets,
                             int* __restrict__ cursors, int n, int total) {
    int i = blockIdx.x * blockDim.x + threadIdx.x;
    if (i < n) {
        int o = excl[i] + blkoff[i / SCAN_BLK];
        offsets[i] = o;
        cursors[i] = o;
    }
    if (i == 0) offsets[n] = total;
}

__global__ void fill_kernel(const int* __restrict__ node_idx,
                            const int* __restrict__ edge_idx,
                            int* __restrict__ cursors,
                            int* __restrict__ entries, int nnz) {
    int p = blockIdx.x * blockDim.x + threadIdx.x;
    if (p >= nnz) return;
    int n = node_idx[p];
    int e = edge_idx[p];
    int s1 = atomicAdd(&cursors[e], 1);
    entries[s1] = n;
    int s2 = atomicAdd(&cursors[N_EDGES + n], 1);
    entries[s2] = e;
}

// ---------------- tf32 GEMM + bias + sigmoid -> fp16 out ---------------------
// out[m][n] = sigmoid( XA[m][0:128] @ W[n][0:128] (+ XB[m][0:128] @ W[n][128:256])
//                      + bias[n] )
// Block 256 thr = 8 warps in 4x2; warp tile 32x64; BK=32.
template <bool TWO>
__global__ void __launch_bounds__(256) gemm_tf32_sig_kernel(
    const float* __restrict__ XA, const float* __restrict__ XB,
    const float* __restrict__ W, const float* __restrict__ bias,
    __half* __restrict__ out, int M)
{
    __shared__ uint32_t Xs[128][36];
    __shared__ uint32_t Ws[128][36];

    const int t    = threadIdx.x;
    const int lane = t & 31;
    const int wid  = t >> 5;
    const int wr   = wid >> 1;        // 0..3, 32 m-rows each
    const int wc   = wid & 1;         // 0..1, 64 n-cols each
    const int g    = lane >> 2;       // group id 0..7
    const int tig  = lane & 3;        // thread in group 0..3
    const int m0   = blockIdx.x * 128;
    const int KTOT = TWO ? 256 : 128;

    float acc[2][8][4];
#pragma unroll
    for (int mt = 0; mt < 2; mt++)
#pragma unroll
        for (int nt = 0; nt < 8; nt++)
#pragma unroll
            for (int i = 0; i < 4; i++) acc[mt][nt][i] = 0.f;

    for (int kc = 0; kc < KTOT; kc += 32) {
        const float* Xsrc = (TWO && kc >= 128) ? XB : XA;
        const int koff    = (TWO && kc >= 128) ? kc - 128 : kc;

        // X tile: 128 rows x 32 cols = 1024 float4 slots
#pragma unroll
        for (int it = 0; it < 4; it++) {
            int i  = t + it * 256;
            int m  = i >> 3;
            int c4 = (i & 7) * 4;
            float4 v = make_float4(0.f, 0.f, 0.f, 0.f);
            if (m0 + m < M)
                v = *(const float4*)(Xsrc + (size_t)(m0 + m) * F + koff + c4);
            Xs[m][c4 + 0] = f2tf32(v.x);
            Xs[m][c4 + 1] = f2tf32(v.y);
            Xs[m][c4 + 2] = f2tf32(v.z);
            Xs[m][c4 + 3] = f2tf32(v.w);
        }
        // W tile: Ws[n][k]
#pragma unroll
        for (int it = 0; it < 4; it++) {
            int i  = t + it * 256;
            int n  = i >> 3;
            int c4 = (i & 7) * 4;
            float4 v = *(const float4*)(W + (size_t)n * KTOT + kc + c4);
            Ws[n][c4 + 0] = f2tf32(v.x);
            Ws[n][c4 + 1] = f2tf32(v.y);
            Ws[n][c4 + 2] = f2tf32(v.z);
            Ws[n][c4 + 3] = f2tf32(v.w);
        }
        __syncthreads();

#pragma unroll
        for (int ks = 0; ks < 32; ks += 8) {
            uint32_t a[2][4];
#pragma unroll
            for (int mt = 0; mt < 2; mt++) {
                int mrow = wr * 32 + mt * 16 + g;
                a[mt][0] = Xs[mrow][ks + tig];
                a[mt][1] = Xs[mrow + 8][ks + tig];
                a[mt][2] = Xs[mrow][ks + tig + 4];
                a[mt][3] = Xs[mrow + 8][ks + tig + 4];
            }
#pragma unroll
            for (int nt = 0; nt < 8; nt++) {
                int nrow = wc * 64 + nt * 8 + g;
                uint32_t b0 = Ws[nrow][ks + tig];
                uint32_t b1 = Ws[nrow][ks + tig + 4];
                mma_tf32(acc[0][nt], a[0][0], a[0][1], a[0][2], a[0][3], b0, b1);
                mma_tf32(acc[1][nt], a[1][0], a[1][1], a[1][2], a[1][3], b0, b1);
            }
        }
        __syncthreads();
    }

    // epilogue: + bias, sigmoid, fp16 store
#pragma unroll
    for (int mt = 0; mt < 2; mt++) {
        int r0 = m0 + wr * 32 + mt * 16 + g;
        int r1 = r0 + 8;
#pragma unroll
        for (int nt = 0; nt < 8; nt++) {
            int col = wc * 64 + nt * 8 + 2 * tig;
            float bb0 = __ldg(bias + col);
            float bb1 = __ldg(bias + col + 1);
            if (r0 < M) {
                __half2 h = __floats2half2_rn(sigmoidf(acc[mt][nt][0] + bb0),
                                              sigmoidf(acc[mt][nt][1] + bb1));
                *(__half2*)(out + (size_t)r0 * F + col) = h;
            }
            if (r1 < M) {
                __half2 h = __floats2half2_rn(sigmoidf(acc[mt][nt][2] + bb0),
                                              sigmoidf(acc[mt][nt][3] + bb1));
                *(__half2*)(out + (size_t)r1 * F + col) = h;
            }
        }
    }
}

// ---------------- segment sum (fp16 gather) + fused bn/sigmoid epilogue ------
// one warp per segment; lane covers features [lane*4, lane*4+4).
// WRITE_AGG: also store raw fp32 sum (edge direction, feeds GEMM2).
template <bool WRITE_AGG>
__global__ void __launch_bounds__(256) segsum_fin_kernel(
    const __half* __restrict__ src,
    const int* __restrict__ entries,
    const int* __restrict__ offsets,       // already segbase-shifted
    const float* __restrict__ x,           // residual input rows
    const float* __restrict__ gamma, const float* __restrict__ beta,
    const float* __restrict__ mean, const float* __restrict__ var,
    float* __restrict__ agg,               // may be null when !WRITE_AGG
    float* __restrict__ out, int nseg)
{
    int w = (int)((blockIdx.x * (size_t)blockDim.x + threadIdx.x) >> 5);
    if (w >= nseg) return;
    int lane = threadIdx.x & 31;
    int beg = __ldg(offsets + w);
    int end = __ldg(offsets + w + 1);

    float4 a0 = make_float4(0.f, 0.f, 0.f, 0.f);
    float4 a1 = a0, a2 = a0, a3 = a0;

    const uint2* s = (const uint2*)src;
    int j = beg;
    for (; j + 4 <= end; j += 4) {
        int e0 = __ldg(entries + j);
        int e1 = __ldg(entries + j + 1);
        int e2 = __ldg(entries + j + 2);
        int e3 = __ldg(entries + j + 3);
        uint2 h0 = __ldg(s + (size_t)e0 * 32 + lane);
        uint2 h1 = __ldg(s + (size_t)e1 * 32 + lane);
        uint2 h2 = __ldg(s + (size_t)e2 * 32 + lane);
        uint2 h3 = __ldg(s + (size_t)e3 * 32 + lane);
        {
            float2 f0 = __half22float2(*(__half2*)&h0.x);
            float2 f1 = __half22float2(*(__half2*)&h0.y);
            a0.x += f0.x; a0.y += f0.y; a0.z += f1.x; a0.w += f1.y;
        }
        {
            float2 f0 = __half22float2(*(__half2*)&h1.x);
            float2 f1 = __half22float2(*(__half2*)&h1.y);
            a1.x += f0.x; a1.y += f0.y; a1.z += f1.x; a1.w += f1.y;
        }
        {
            float2 f0 = __half22float2(*(__half2*)&h2.x);
            float2 f1 = __half22float2(*(__half2*)&h2.y);
            a2.x += f0.x; a2.y += f0.y; a2.z += f1.x; a2.w += f1.y;
        }
        {
            float2 f0 = __half22float2(*(__half2*)&h3.x);
            float2 f1 = __half22float2(*(__half2*)&h3.y);
            a3.x += f0.x; a3.y += f0.y; a3.z += f1.x; a3.w += f1.y;
        }
    }
    for (; j < end; j++) {
        int e = __ldg(entries + j);
        uint2 h = __ldg(s + (size_t)e * 32 + lane);
        float2 f0 = __half22float2(*(__half2*)&h.x);
        float2 f1 = __half22float2(*(__half2*)&h.y);
        a0.x += f0.x; a0.y += f0.y; a0.z += f1.x; a0.w += f1.y;
    }
    float4 r;
    r.x = (a0.x + a1.x) + (a2.x + a3.x);
    r.y = (a0.y + a1.y) + (a2.y + a3.y);
    r.z = (a0.z + a1.z) + (a2.z + a3.z);
    r.w = (a0.w + a1.w) + (a2.w + a3.w);

    if (WRITE_AGG)
        *((float4*)agg + (size_t)w * 32 + lane) = r;

    // fused epilogue: sigmoid(bn(x) + r)
    float4 xv = __ldg((const float4*)x + (size_t)w * 32 + lane);
    float4 ga = __ldg((const float4*)gamma + lane);
    float4 be = __ldg((const float4*)beta + lane);
    float4 me = __ldg((const float4*)mean + lane);
    float4 va = __ldg((const float4*)var + lane);
    float4 o;
    o.x = sigmoidf((xv.x - me.x) * (ga.x * rsqrtf(va.x + 1e-5f)) + be.x + r.x);
    o.y = sigmoidf((xv.y - me.y) * (ga.y * rsqrtf(va.y + 1e-5f)) + be.y + r.y);
    o.z = sigmoidf((xv.z - me.z) * (ga.z * rsqrtf(va.z + 1e-5f)) + be.z + r.z);
    o.w = sigmoidf((xv.w - me.w) * (ga.w * rsqrtf(va.w + 1e-5f)) + be.w + r.w);
    *((float4*)out + (size_t)w * 32 + lane) = o;
}

// ---------------- launch -----------------------------------------------------
extern "C" void kernel_launch(void* const* d_in, const int* in_sizes, int n_in,
                              void* d_out, int out_size)
{
    const float* x0        = (const float*)d_in[0];
    const float* x1        = (const float*)d_in[1];
    const int*   node_idx  = (const int*)d_in[2];
    const int*   edge_idx  = (const int*)d_in[3];
    const float* W_nh      = (const float*)d_in[4];
    const float* b_nh      = (const float*)d_in[5];
    const float* W_en      = (const float*)d_in[6];
    const float* b_en      = (const float*)d_in[7];
    const float* bn0_gamma = (const float*)d_in[8];
    const float* bn0_beta  = (const float*)d_in[9];
    const float* bn0_mean  = (const float*)d_in[10];
    const float* bn0_var   = (const float*)d_in[11];
    const float* bn1_gamma = (const float*)d_in[12];
    const float* bn1_beta  = (const float*)d_in[13];
    const float* bn1_mean  = (const float*)d_in[14];
    const float* bn1_var   = (const float*)d_in[15];

    float* out = (float*)d_out;
    const int nnz = in_sizes[2];

    __half *node_msg, *he_msg;
    float *edge_agg;
    int *cnt, *excl, *blksum, *blkoff, *offsets, *cursors, *entries;
    cudaGetSymbolAddress((void**)&node_msg, g_node_msg);
    cudaGetSymbolAddress((void**)&edge_agg, g_edge_agg);
    cudaGetSymbolAddress((void**)&he_msg,   g_he_msg);
    cudaGetSymbolAddress((void**)&cnt,      g_cnt);
    cudaGetSymbolAddress((void**)&excl,     g_excl);
    cudaGetSymbolAddress((void**)&blksum,   g_blksum);
    cudaGetSymbolAddress((void**)&blkoff,   g_blkoff);
    cudaGetSymbolAddress((void**)&offsets,  g_offsets);
    cudaGetSymbolAddress((void**)&cursors,  g_cursors);
    cudaGetSymbolAddress((void**)&entries,  g_entries);

    // --- CSR build ---
    zero_int_kernel<<<(NSEG + 255) / 256, 256>>>(cnt, NSEG);
    hist_kernel<<<(nnz + 255) / 256, 256>>>(node_idx, edge_idx, cnt, nnz);
    scan1_kernel<<<NBLK, SCAN_BLK>>>(cnt, excl, blksum, NSEG);
    scan2_kernel<<<1, 128>>>(blksum, blkoff, NBLK);
    scan3_kernel<<<(NSEG + 255) / 256, 256>>>(excl, blkoff, offsets, cursors,
                                              NSEG, 2 * nnz);
    fill_kernel<<<(nnz + 255) / 256, 256>>>(node_idx, edge_idx, cursors,
                                            entries, nnz);

    // 1) node messages: sigmoid(x0 @ Wnh^T + b)  -> fp16
    gemm_tf32_sig_kernel<false><<<(N_NODES + 127) / 128, 256>>>(
        x0, nullptr, W_nh, b_nh, node_msg, N_NODES);

    // 2) edge segments: agg (fp32) + fused x1_out epilogue
    segsum_fin_kernel<true><<<(N_EDGES * 32 + 255) / 256, 256>>>(
        node_msg, entries, offsets, x1,
        bn1_gamma, bn1_beta, bn1_mean, bn1_var,
        edge_agg, out + (size_t)N_NODES * F, N_EDGES);

    // 3) hyperedge messages: sigmoid(cat(x1, edge_agg) @ Wen^T + b) -> fp16
    gemm_tf32_sig_kernel<true><<<(N_EDGES + 127) / 128, 256>>>(
        x1, edge_agg, W_en, b_en, he_msg, N_EDGES);

    // 4) node segments: fused x0_out epilogue (no scratch store)
    segsum_fin_kernel<false><<<(N_NODES * 32 + 255) / 256, 256>>>(
        he_msg, entries, offsets + N_EDGES, x0,
        bn0_gamma, bn0_beta, bn0_mean, bn0_var,
        nullptr, out, N_NODES);
}